// round 14
// baseline (speedup 1.0000x reference)
#include <cuda_runtime.h>
#include <cuda_bf16.h>
#include <cstdint>

// Problem shape (fixed by reference setup_inputs)
#define B_    16
#define C_    384
#define CR_   96
#define HW_   12544          // 112*112
#define HW4_  3136           // HW/4 (float4 per plane); 3136 = 448*7 exactly
#define NPLANES_ (B_ * C_)   // 6144
#define T_    448
#define K_    7

// First WT_CTAS_ scale-CTAs (the L2-hot reuse window, ~103MB of output)
// write through (no L2 allocation); the rest use evict-first allocate.
#define WT_CTAS_ 2048

// Scratch (no cudaMalloc allowed) — device globals.
__device__ float g_mean[NPLANES_];
__device__ float g_t[B_ * CR_];

// ---------------------------------------------------------------------------
// Kernel 1: per-plane mean. One CTA per plane. At DRAM roofline (~84%).
// Ascending order: x's tail is freshest in L2 at kernel end.
// ---------------------------------------------------------------------------
__global__ void __launch_bounds__(T_) se_reduce_kernel(const float* __restrict__ x) {
    const int plane = blockIdx.x;
    const float4* __restrict__ p =
        reinterpret_cast<const float4*>(x) + (size_t)plane * HW4_;

    float4 v[K_];
    #pragma unroll
    for (int k = 0; k < K_; k++)
        v[k] = p[threadIdx.x + k * T_];

    float sum = 0.0f;
    #pragma unroll
    for (int k = 0; k < K_; k++)
        sum += (v[k].x + v[k].y) + (v[k].z + v[k].w);

    #pragma unroll
    for (int o = 16; o > 0; o >>= 1)
        sum += __shfl_down_sync(0xffffffffu, sum, o);

    __shared__ float sdata[T_ / 32];
    const int lane = threadIdx.x & 31;
    const int wid  = threadIdx.x >> 5;
    if (lane == 0) sdata[wid] = sum;
    __syncthreads();
    if (wid == 0) {
        sum = (lane < (T_ / 32)) ? sdata[lane] : 0.0f;
        #pragma unroll
        for (int o = 8; o > 0; o >>= 1)
            sum += __shfl_down_sync(0xffffffffu, sum, o);
        if (lane == 0) g_mean[plane] = sum * (1.0f / (float)HW_);
    }
}

// ---------------------------------------------------------------------------
// Kernel 2: fc1 — one warp per (b,r) dot, no per-warp loop. ~2us.
// ---------------------------------------------------------------------------
__global__ void __launch_bounds__(128) se_fc1_kernel(const float* __restrict__ w1,
                                                     const float* __restrict__ b1) {
    const int lane = threadIdx.x & 31;
    const int d    = blockIdx.x * 4 + (threadIdx.x >> 5);   // 0..1535
    const int b    = d / CR_;
    const int r    = d % CR_;

    const float4* __restrict__ wr4 =
        reinterpret_cast<const float4*>(w1 + r * C_);
    const float4* __restrict__ sb4 =
        reinterpret_cast<const float4*>(g_mean + b * C_);

    float acc = 0.0f;
    #pragma unroll
    for (int k = 0; k < 3; k++) {
        const int i4 = lane + 32 * k;
        const float4 wv = __ldg(&wr4[i4]);
        const float4 sv = sb4[i4];
        acc = fmaf(wv.x, sv.x, acc);
        acc = fmaf(wv.y, sv.y, acc);
        acc = fmaf(wv.z, sv.z, acc);
        acc = fmaf(wv.w, sv.w, acc);
    }
    #pragma unroll
    for (int o = 16; o > 0; o >>= 1)
        acc += __shfl_down_sync(0xffffffffu, acc, o);
    if (lane == 0) g_t[d] = fmaxf(acc + __ldg(&b1[r]), 0.0f);
}

// ---------------------------------------------------------------------------
// Kernel 3: fused fc2 + broadcast multiply.
// Reverse plane order (L2-hot tail first). Hybrid stores: write-through for
// the hot window (protects L2 read reuse), evict-first allocate afterwards.
// ---------------------------------------------------------------------------
__global__ void __launch_bounds__(T_) se_scale_kernel(const float* __restrict__ x,
                                                      const float* __restrict__ w2,
                                                      const float* __restrict__ b2,
                                                      float* __restrict__ out) {
    const int plane = (NPLANES_ - 1) - blockIdx.x;
    const int b = plane / C_;
    const int c = plane % C_;

    const float4* __restrict__ p =
        reinterpret_cast<const float4*>(x) + (size_t)plane * HW4_;
    float4* __restrict__ o =
        reinterpret_cast<float4*>(out) + (size_t)plane * HW4_;
    const int tid  = threadIdx.x;
    const int lane = tid & 31;
    const int wid  = tid >> 5;

    __shared__ float s_sc;

    // (1) Issue the plane's loads first — independent of the scale factor.
    float4 v[K_];
    #pragma unroll
    for (int k = 0; k < K_; k++)
        v[k] = __ldcs(&p[tid + k * T_]);

    // (2) Warp 0 computes this plane's scale factor while loads are in flight.
    if (wid == 0) {
        const float* __restrict__ wc = w2 + c * CR_;
        const float* __restrict__ tb = g_t + b * CR_;
        float acc = 0.0f;
        #pragma unroll
        for (int k = 0; k < 3; k++) {
            const int r = lane + 32 * k;
            acc = fmaf(__ldg(&wc[r]), tb[r], acc);
        }
        #pragma unroll
        for (int off = 16; off > 0; off >>= 1)
            acc += __shfl_down_sync(0xffffffffu, acc, off);
        if (lane == 0)
            s_sc = __saturatef(fmaf(acc + __ldg(&b2[c]), 1.0f / 6.0f, 0.5f));
    }
    __syncthreads();

    // (3) Multiply and stream out — wt in the hot window, cs elsewhere.
    const float sc = s_sc;
    if (blockIdx.x < WT_CTAS_) {
        #pragma unroll
        for (int k = 0; k < K_; k++) {
            v[k].x *= sc; v[k].y *= sc; v[k].z *= sc; v[k].w *= sc;
            __stwt(&o[tid + k * T_], v[k]);
        }
    } else {
        #pragma unroll
        for (int k = 0; k < K_; k++) {
            v[k].x *= sc; v[k].y *= sc; v[k].z *= sc; v[k].w *= sc;
            __stcs(&o[tid + k * T_], v[k]);
        }
    }
}

// ---------------------------------------------------------------------------
extern "C" void kernel_launch(void* const* d_in, const int* in_sizes, int n_in,
                              void* d_out, int out_size) {
    const float* x  = (const float*)d_in[0];
    const float* w1 = (const float*)d_in[1];
    const float* b1 = (const float*)d_in[2];
    const float* w2 = (const float*)d_in[3];
    const float* b2 = (const float*)d_in[4];
    float* out = (float*)d_out;

    se_reduce_kernel<<<NPLANES_, T_>>>(x);
    se_fc1_kernel<<<(B_ * CR_) / 4, 128>>>(w1, b1);
    se_scale_kernel<<<NPLANES_, T_>>>(x, w2, b2, out);
}

// round 15
// speedup vs baseline: 1.0338x; 1.0338x over previous
#include <cuda_runtime.h>
#include <cuda_bf16.h>
#include <cstdint>

// Problem shape (fixed by reference setup_inputs)
#define B_    16
#define C_    384
#define CR_   96
#define HW_   12544          // 112*112
#define HW4_  3136           // HW/4 (float4 per plane); 3136 = 448*7 exactly
#define NPLANES_ (B_ * C_)   // 6144
#define T_    448
#define K_    7

// Scratch (no cudaMalloc allowed) — device globals.
__device__ float g_mean[NPLANES_];
__device__ float g_t[B_ * CR_];

__device__ __forceinline__ void gdc_launch_dependents() {
    asm volatile("griddepcontrol.launch_dependents;");
}
__device__ __forceinline__ void gdc_wait() {
    asm volatile("griddepcontrol.wait;" ::: "memory");
}

// ---------------------------------------------------------------------------
// Kernel 1: per-plane mean. One CTA per plane. ~84% DRAM (roofline).
// launch_dependents at start: fires when the last wave launches, letting fc1
// spin up under the reduce tail.
// ---------------------------------------------------------------------------
__global__ void __launch_bounds__(T_) se_reduce_kernel(const float* __restrict__ x) {
    gdc_launch_dependents();

    const int plane = blockIdx.x;
    const float4* __restrict__ p =
        reinterpret_cast<const float4*>(x) + (size_t)plane * HW4_;

    float4 v[K_];
    #pragma unroll
    for (int k = 0; k < K_; k++)
        v[k] = p[threadIdx.x + k * T_];

    float sum = 0.0f;
    #pragma unroll
    for (int k = 0; k < K_; k++)
        sum += (v[k].x + v[k].y) + (v[k].z + v[k].w);

    #pragma unroll
    for (int o = 16; o > 0; o >>= 1)
        sum += __shfl_down_sync(0xffffffffu, sum, o);

    __shared__ float sdata[T_ / 32];
    const int lane = threadIdx.x & 31;
    const int wid  = threadIdx.x >> 5;
    if (lane == 0) sdata[wid] = sum;
    __syncthreads();
    if (wid == 0) {
        sum = (lane < (T_ / 32)) ? sdata[lane] : 0.0f;
        #pragma unroll
        for (int o = 8; o > 0; o >>= 1)
            sum += __shfl_down_sync(0xffffffffu, sum, o);
        if (lane == 0) g_mean[plane] = sum * (1.0f / (float)HW_);
    }
}

// ---------------------------------------------------------------------------
// Kernel 2: fc1 — one warp per (b,r) dot. PDL: prefetch w1/b1 (independent of
// reduce), then wait for g_mean, then finish the dot.
// ---------------------------------------------------------------------------
__global__ void __launch_bounds__(128) se_fc1_kernel(const float* __restrict__ w1,
                                                     const float* __restrict__ b1) {
    gdc_launch_dependents();

    const int lane = threadIdx.x & 31;
    const int d    = blockIdx.x * 4 + (threadIdx.x >> 5);   // 0..1535
    const int b    = d / CR_;
    const int r    = d % CR_;

    const float4* __restrict__ wr4 =
        reinterpret_cast<const float4*>(w1 + r * C_);

    // Pre-wait: weight loads don't depend on the reduce kernel.
    float4 wv[3];
    #pragma unroll
    for (int k = 0; k < 3; k++)
        wv[k] = __ldg(&wr4[lane + 32 * k]);
    const float bias = __ldg(&b1[r]);

    gdc_wait();   // g_mean now visible

    const float4* __restrict__ sb4 =
        reinterpret_cast<const float4*>(g_mean + b * C_);
    float acc = 0.0f;
    #pragma unroll
    for (int k = 0; k < 3; k++) {
        const float4 sv = sb4[lane + 32 * k];
        acc = fmaf(wv[k].x, sv.x, acc);
        acc = fmaf(wv[k].y, sv.y, acc);
        acc = fmaf(wv[k].z, sv.z, acc);
        acc = fmaf(wv[k].w, sv.w, acc);
    }
    #pragma unroll
    for (int o = 16; o > 0; o >>= 1)
        acc += __shfl_down_sync(0xffffffffu, acc, o);
    if (lane == 0) g_t[d] = fmaxf(acc + bias, 0.0f);
}

// ---------------------------------------------------------------------------
// Kernel 3: fused fc2 + broadcast multiply. PDL: issue ALL x-loads and w2
// loads pre-wait (independent of fc1), wait, then read g_t and finish.
// Reverse plane order (L2-hot tail first); __ldcs / __stcs.
// ---------------------------------------------------------------------------
__global__ void __launch_bounds__(T_) se_scale_kernel(const float* __restrict__ x,
                                                      const float* __restrict__ w2,
                                                      const float* __restrict__ b2,
                                                      float* __restrict__ out) {
    const int plane = (NPLANES_ - 1) - blockIdx.x;
    const int b = plane / C_;
    const int c = plane % C_;

    const float4* __restrict__ p =
        reinterpret_cast<const float4*>(x) + (size_t)plane * HW4_;
    float4* __restrict__ o =
        reinterpret_cast<float4*>(out) + (size_t)plane * HW4_;
    const int tid  = threadIdx.x;
    const int lane = tid & 31;
    const int wid  = tid >> 5;

    __shared__ float s_sc;

    // ---- Pre-wait section: nothing here depends on fc1 ----
    float4 v[K_];
    #pragma unroll
    for (int k = 0; k < K_; k++)
        v[k] = __ldcs(&p[tid + k * T_]);

    float wreg[3];
    float breg = 0.0f;
    if (wid == 0) {
        const float* __restrict__ wc = w2 + c * CR_;
        #pragma unroll
        for (int k = 0; k < 3; k++)
            wreg[k] = __ldg(&wc[lane + 32 * k]);
        breg = __ldg(&b2[c]);
    }

    gdc_wait();   // g_t now visible

    // ---- Post-wait: warp 0 computes the scale factor ----
    if (wid == 0) {
        const float* __restrict__ tb = g_t + b * CR_;
        float acc = 0.0f;
        #pragma unroll
        for (int k = 0; k < 3; k++)
            acc = fmaf(wreg[k], tb[lane + 32 * k], acc);
        #pragma unroll
        for (int off = 16; off > 0; off >>= 1)
            acc += __shfl_down_sync(0xffffffffu, acc, off);
        if (lane == 0)
            s_sc = __saturatef(fmaf(acc + breg, 1.0f / 6.0f, 0.5f));
    }
    __syncthreads();

    const float sc = s_sc;
    #pragma unroll
    for (int k = 0; k < K_; k++) {
        v[k].x *= sc; v[k].y *= sc; v[k].z *= sc; v[k].w *= sc;
        __stcs(&o[tid + k * T_], v[k]);
    }
}

// ---------------------------------------------------------------------------
// Launch chain with Programmatic Dependent Launch on fc1 and scale.
// ---------------------------------------------------------------------------
static void launch_pdl(void* func, dim3 grid, dim3 block, void** args,
                       cudaStream_t stream) {
    cudaLaunchConfig_t cfg = {};
    cfg.gridDim = grid;
    cfg.blockDim = block;
    cfg.dynamicSmemBytes = 0;
    cfg.stream = stream;
    cudaLaunchAttribute attr[1];
    attr[0].id = cudaLaunchAttributeProgrammaticStreamSerialization;
    attr[0].val.programmaticStreamSerializationAllowed = 1;
    cfg.attrs = attr;
    cfg.numAttrs = 1;
    cudaLaunchKernelExC(&cfg, func, args);
}

extern "C" void kernel_launch(void* const* d_in, const int* in_sizes, int n_in,
                              void* d_out, int out_size) {
    const float* x  = (const float*)d_in[0];
    const float* w1 = (const float*)d_in[1];
    const float* b1 = (const float*)d_in[2];
    const float* w2 = (const float*)d_in[3];
    const float* b2 = (const float*)d_in[4];
    float* out = (float*)d_out;

    se_reduce_kernel<<<NPLANES_, T_>>>(x);

    {
        void* args[] = { (void*)&w1, (void*)&b1 };
        launch_pdl((void*)se_fc1_kernel, dim3((B_ * CR_) / 4), dim3(128),
                   args, 0);
    }
    {
        void* args[] = { (void*)&x, (void*)&w2, (void*)&b2, (void*)&out };
        launch_pdl((void*)se_scale_kernel, dim3(NPLANES_), dim3(T_),
                   args, 0);
    }
}

// round 17
// speedup vs baseline: 1.0624x; 1.0276x over previous
#include <cuda_runtime.h>
#include <cuda_bf16.h>
#include <cstdint>

// Problem shape (fixed by reference setup_inputs)
#define B_    16
#define C_    384
#define CR_   96
#define HW_   12544          // 112*112
#define HW4_  3136           // float4 per plane; 3136 = 448*7 exactly
#define HW8_  1568           // 32B chunks per plane; 1568 = 448*3 + 224
#define NPLANES_ (B_ * C_)   // 6144
#define T_    448
#define K_    7

// Hot tail: last HOT_PLANES_ planes (~115MB < 126MB L2) loaded evict_last in
// reduce so they survive until scale re-reads them (scale runs tail-first).
#define HOT_PLANES_ 2300
#define COLD_LIMIT_ (NPLANES_ - HOT_PLANES_)

// Scratch (no cudaMalloc allowed) — device globals.
__device__ float g_mean[NPLANES_];
__device__ float g_t[B_ * CR_];

__device__ __forceinline__ void gdc_launch_dependents() {
    asm volatile("griddepcontrol.launch_dependents;");
}
__device__ __forceinline__ void gdc_wait() {
    asm volatile("griddepcontrol.wait;" ::: "memory");
}

// 256-bit evict_last load (sm_103 requires v8.b32 for this modifier).
__device__ __forceinline__ void ld_evict_last_32B(const float4* p,
                                                  float4& a, float4& b) {
    asm volatile("ld.global.L2::evict_last.v8.b32 "
                 "{%0,%1,%2,%3,%4,%5,%6,%7}, [%8];"
                 : "=f"(a.x), "=f"(a.y), "=f"(a.z), "=f"(a.w),
                   "=f"(b.x), "=f"(b.y), "=f"(b.z), "=f"(b.w)
                 : "l"(p));
}
__device__ __forceinline__ float4 ld_cs(const float4* p) {
    float4 v;
    asm volatile("ld.global.cs.v4.f32 {%0,%1,%2,%3}, [%4];"
                 : "=f"(v.x), "=f"(v.y), "=f"(v.z), "=f"(v.w)
                 : "l"(p));
    return v;
}

// ---------------------------------------------------------------------------
// Kernel 1: per-plane mean. Cold planes: evict-first float4 loads.
// Hot tail planes: 256-bit evict_last loads (3 full rounds + half round).
// ---------------------------------------------------------------------------
__global__ void __launch_bounds__(T_) se_reduce_kernel(const float* __restrict__ x) {
    gdc_launch_dependents();

    const int plane = blockIdx.x;
    const int tid   = threadIdx.x;
    const float4* __restrict__ p =
        reinterpret_cast<const float4*>(x) + (size_t)plane * HW4_;

    float sum = 0.0f;
    if (plane < COLD_LIMIT_) {
        float4 v[K_];
        #pragma unroll
        for (int k = 0; k < K_; k++)
            v[k] = ld_cs(&p[tid + k * T_]);
        #pragma unroll
        for (int k = 0; k < K_; k++)
            sum += (v[k].x + v[k].y) + (v[k].z + v[k].w);
    } else {
        // 32B chunks: chunk ci covers float4 pair (2*ci, 2*ci+1).
        float4 a[4], b[4];
        #pragma unroll
        for (int k = 0; k < 3; k++)
            ld_evict_last_32B(&p[2 * (tid + k * T_)], a[k], b[k]);
        const bool extra = (tid < HW8_ - 3 * T_);   // tid < 224
        if (extra)
            ld_evict_last_32B(&p[2 * (tid + 3 * T_)], a[3], b[3]);
        #pragma unroll
        for (int k = 0; k < 3; k++)
            sum += (a[k].x + a[k].y) + (a[k].z + a[k].w)
                 + (b[k].x + b[k].y) + (b[k].z + b[k].w);
        if (extra)
            sum += (a[3].x + a[3].y) + (a[3].z + a[3].w)
                 + (b[3].x + b[3].y) + (b[3].z + b[3].w);
    }

    #pragma unroll
    for (int o = 16; o > 0; o >>= 1)
        sum += __shfl_down_sync(0xffffffffu, sum, o);

    __shared__ float sdata[T_ / 32];
    const int lane = tid & 31;
    const int wid  = tid >> 5;
    if (lane == 0) sdata[wid] = sum;
    __syncthreads();
    if (wid == 0) {
        sum = (lane < (T_ / 32)) ? sdata[lane] : 0.0f;
        #pragma unroll
        for (int o = 8; o > 0; o >>= 1)
            sum += __shfl_down_sync(0xffffffffu, sum, o);
        if (lane == 0) g_mean[plane] = sum * (1.0f / (float)HW_);
    }
}

// ---------------------------------------------------------------------------
// Kernel 2: fc1 — one warp per (b,r) dot. PDL: prefetch w1/b1 pre-wait.
// ---------------------------------------------------------------------------
__global__ void __launch_bounds__(128) se_fc1_kernel(const float* __restrict__ w1,
                                                     const float* __restrict__ b1) {
    gdc_launch_dependents();

    const int lane = threadIdx.x & 31;
    const int d    = blockIdx.x * 4 + (threadIdx.x >> 5);   // 0..1535
    const int b    = d / CR_;
    const int r    = d % CR_;

    const float4* __restrict__ wr4 =
        reinterpret_cast<const float4*>(w1 + r * C_);

    float4 wv[3];
    #pragma unroll
    for (int k = 0; k < 3; k++)
        wv[k] = __ldg(&wr4[lane + 32 * k]);
    const float bias = __ldg(&b1[r]);

    gdc_wait();   // g_mean now visible

    const float4* __restrict__ sb4 =
        reinterpret_cast<const float4*>(g_mean + b * C_);
    float acc = 0.0f;
    #pragma unroll
    for (int k = 0; k < 3; k++) {
        const float4 sv = sb4[lane + 32 * k];
        acc = fmaf(wv[k].x, sv.x, acc);
        acc = fmaf(wv[k].y, sv.y, acc);
        acc = fmaf(wv[k].z, sv.z, acc);
        acc = fmaf(wv[k].w, sv.w, acc);
    }
    #pragma unroll
    for (int o = 16; o > 0; o >>= 1)
        acc += __shfl_down_sync(0xffffffffu, acc, o);
    if (lane == 0) g_t[d] = fmaxf(acc + bias, 0.0f);
}

// ---------------------------------------------------------------------------
// Kernel 3: fused fc2 + broadcast multiply. PDL pre-wait: x-loads + w2 loads.
// Reverse plane order (hot tail first). __ldcs demotes hits; __stcs stores.
// ---------------------------------------------------------------------------
__global__ void __launch_bounds__(T_) se_scale_kernel(const float* __restrict__ x,
                                                      const float* __restrict__ w2,
                                                      const float* __restrict__ b2,
                                                      float* __restrict__ out) {
    const int plane = (NPLANES_ - 1) - blockIdx.x;
    const int b = plane / C_;
    const int c = plane % C_;

    const float4* __restrict__ p =
        reinterpret_cast<const float4*>(x) + (size_t)plane * HW4_;
    float4* __restrict__ o =
        reinterpret_cast<float4*>(out) + (size_t)plane * HW4_;
    const int tid  = threadIdx.x;
    const int lane = tid & 31;
    const int wid  = tid >> 5;

    __shared__ float s_sc;

    // ---- Pre-wait: nothing here depends on fc1 ----
    float4 v[K_];
    #pragma unroll
    for (int k = 0; k < K_; k++)
        v[k] = __ldcs(&p[tid + k * T_]);

    float wreg[3];
    float breg = 0.0f;
    if (wid == 0) {
        const float* __restrict__ wc = w2 + c * CR_;
        #pragma unroll
        for (int k = 0; k < 3; k++)
            wreg[k] = __ldg(&wc[lane + 32 * k]);
        breg = __ldg(&b2[c]);
    }

    gdc_wait();   // g_t now visible

    if (wid == 0) {
        const float* __restrict__ tb = g_t + b * CR_;
        float acc = 0.0f;
        #pragma unroll
        for (int k = 0; k < 3; k++)
            acc = fmaf(wreg[k], tb[lane + 32 * k], acc);
        #pragma unroll
        for (int off = 16; off > 0; off >>= 1)
            acc += __shfl_down_sync(0xffffffffu, acc, off);
        if (lane == 0)
            s_sc = __saturatef(fmaf(acc + breg, 1.0f / 6.0f, 0.5f));
    }
    __syncthreads();

    const float sc = s_sc;
    #pragma unroll
    for (int k = 0; k < K_; k++) {
        v[k].x *= sc; v[k].y *= sc; v[k].z *= sc; v[k].w *= sc;
        __stcs(&o[tid + k * T_], v[k]);
    }
}

// ---------------------------------------------------------------------------
static void launch_pdl(void* func, dim3 grid, dim3 block, void** args,
                       cudaStream_t stream) {
    cudaLaunchConfig_t cfg = {};
    cfg.gridDim = grid;
    cfg.blockDim = block;
    cfg.dynamicSmemBytes = 0;
    cfg.stream = stream;
    cudaLaunchAttribute attr[1];
    attr[0].id = cudaLaunchAttributeProgrammaticStreamSerialization;
    attr[0].val.programmaticStreamSerializationAllowed = 1;
    cfg.attrs = attr;
    cfg.numAttrs = 1;
    cudaLaunchKernelExC(&cfg, func, args);
}

extern "C" void kernel_launch(void* const* d_in, const int* in_sizes, int n_in,
                              void* d_out, int out_size) {
    const float* x  = (const float*)d_in[0];
    const float* w1 = (const float*)d_in[1];
    const float* b1 = (const float*)d_in[2];
    const float* w2 = (const float*)d_in[3];
    const float* b2 = (const float*)d_in[4];
    float* out = (float*)d_out;

    se_reduce_kernel<<<NPLANES_, T_>>>(x);

    {
        void* args[] = { (void*)&w1, (void*)&b1 };
        launch_pdl((void*)se_fc1_kernel, dim3((B_ * CR_) / 4), dim3(128),
                   args, 0);
    }
    {
        void* args[] = { (void*)&x, (void*)&w2, (void*)&b2, (void*)&out };
        launch_pdl((void*)se_scale_kernel, dim3(NPLANES_), dim3(T_),
                   args, 0);
    }
}